// round 10
// baseline (speedup 1.0000x reference)
#include <cuda_runtime.h>

#define B_  32
#define T_  4
#define L_  256
#define D_  768
#define H_  12
#define DH_ 64
#define N_  (B_*T_*L_)   // 32768 rows

// ---------------- scratch (no allocations allowed) ----------------
__device__ float g_Hq[(size_t)N_*D_];
__device__ float g_Hk[(size_t)N_*D_];
__device__ float g_Hv[(size_t)N_*D_];
__device__ float g_O [(size_t)N_*D_];
__device__ float g_Y [(size_t)N_*D_];

// ---------------- packed f32x2 helpers (sm_103a) ----------------
__device__ __forceinline__ unsigned long long pack2(float lo, float hi) {
    unsigned long long r;
    asm("mov.b64 %0, {%1, %2};" : "=l"(r) : "f"(lo), "f"(hi));
    return r;
}
__device__ __forceinline__ void unpack2(unsigned long long v, float& lo, float& hi) {
    asm("mov.b64 {%0, %1}, %2;" : "=f"(lo), "=f"(hi) : "l"(v));
}
__device__ __forceinline__ unsigned long long ffma2(
    unsigned long long a, unsigned long long b, unsigned long long c) {
    unsigned long long d;
    asm("fma.rn.f32x2 %0, %1, %2, %3;" : "=l"(d) : "l"(a), "l"(b), "l"(c));
    return d;
}

// ====== GEMM: C[m,n] = bias[n] + sum_k A[m,k]*W[n,k], single ascending-k FMA chain ======
// Bitwise-exact per-element serial chain (matches reference). DO NOT reorder.
__global__ __launch_bounds__(256) void gemm_nt_kernel(
    const float* __restrict__ A, const float* __restrict__ W,
    const float* __restrict__ bias, float* __restrict__ C,
    int K, int Nn)
{
    __shared__ float As[8][128];
    __shared__ float Bs[8][128];
    const int tid  = threadIdx.x;
    const int tx   = tid & 15;
    const int ty   = tid >> 4;
    const int m0   = blockIdx.y * 128;
    const int n0   = blockIdx.x * 128;
    const int arow = tid >> 1;
    const int ak   = (tid & 1) * 4;

    const float* Aptr = A + (size_t)(m0 + arow) * K + ak;
    const float* Wptr = W + (size_t)(n0 + arow) * K + ak;

    unsigned long long acc2[8][4];   // [row][colpair]
#pragma unroll
    for (int i = 0; i < 8; i++)
#pragma unroll
        for (int j = 0; j < 4; j++) acc2[i][j] = 0ULL;

    for (int k0 = 0; k0 < K; k0 += 8) {
        float4 av = *(const float4*)(Aptr + k0);
        float4 wv = *(const float4*)(Wptr + k0);
        __syncthreads();
        As[ak + 0][arow] = av.x; As[ak + 1][arow] = av.y;
        As[ak + 2][arow] = av.z; As[ak + 3][arow] = av.w;
        Bs[ak + 0][arow] = wv.x; Bs[ak + 1][arow] = wv.y;
        Bs[ak + 2][arow] = wv.z; Bs[ak + 3][arow] = wv.w;
        __syncthreads();
#pragma unroll
        for (int kk = 0; kk < 8; kk++) {          // ascending k
            float a[8];
            *(float4*)&a[0] = *(const float4*)&As[kk][ty * 8 + 0];
            *(float4*)&a[4] = *(const float4*)&As[kk][ty * 8 + 4];
            const ulonglong2 b01 = *(const ulonglong2*)&Bs[kk][tx * 8 + 0];
            const ulonglong2 b23 = *(const ulonglong2*)&Bs[kk][tx * 8 + 4];
            unsigned long long b2[4];
            b2[0] = b01.x; b2[1] = b01.y; b2[2] = b23.x; b2[3] = b23.y;
#pragma unroll
            for (int i = 0; i < 8; i++) {
                const unsigned long long a2 = pack2(a[i], a[i]);
#pragma unroll
                for (int j = 0; j < 4; j++)
                    acc2[i][j] = ffma2(a2, b2[j], acc2[i][j]);
            }
        }
    }

#pragma unroll
    for (int i = 0; i < 8; i++) {
        float* cp = C + (size_t)(m0 + ty * 8 + i) * Nn + n0 + tx * 8;
#pragma unroll
        for (int j = 0; j < 4; j++) {
            float c0, c1;
            unpack2(acc2[i][j], c0, c1);
            cp[2 * j + 0] = __fadd_rn(c0, bias[n0 + tx * 8 + 2 * j + 0]);
            cp[2 * j + 1] = __fadd_rn(c1, bias[n0 + tx * 8 + 2 * j + 1]);
        }
    }
}

// ===== LayerNorm + LIF, XLA:CPU (NEON VF=8) reduce — bitwise-sensitive, order untouched =====
// Occupancy-tuned: gamma/beta in smem, float4 staging, <=64 regs (4 blocks/SM).
__global__ __launch_bounds__(256, 4) void ln_lif_kernel(
    const float* __restrict__ Hin, float* __restrict__ Sout,
    const float* __restrict__ gam, const float* __restrict__ bet, float thr)
{
    __shared__ __align__(16) float xs[8][768];
    __shared__ float gs[768];
    __shared__ float bes[768];
    const int w   = threadIdx.x >> 5;
    const int j   = threadIdx.x & 31;
    const int row = blockIdx.x * 8 + w;
    const int b   = row / L_;
    const int l   = row % L_;

    for (int i = threadIdx.x; i < 768; i += 256) {
        gs[i]  = gam[i];
        bes[i] = bet[i];
    }
    __syncthreads();

    float v[24];
#pragma unroll
    for (int k = 0; k < 24; k++) v[k] = 0.0f;

    for (int t = 0; t < T_; t++) {
        const size_t off = ((size_t)(b * T_ + t) * L_ + l) * D_;
#pragma unroll
        for (int qd = 0; qd < 6; qd++) {
            float4 xv = *(const float4*)(Hin + off + 4 * j + 128 * qd);
            *(float4*)&xs[w][4 * j + 128 * qd] = xv;
        }
        __syncwarp();

        // ---- mean: 8-lane stride-8 serial partials (EXACT order) ----
        float p = 0.0f;
        if (j < 8) {
#pragma unroll 8
            for (int i = 0; i < 96; i++)
                p = __fadd_rn(p, xs[w][8 * i + j]);
        }
        p = __fadd_rn(p, __shfl_xor_sync(0xffffffffu, p, 4));
        p = __fadd_rn(p, __shfl_xor_sync(0xffffffffu, p, 1));
        p = __fadd_rn(p, __shfl_xor_sync(0xffffffffu, p, 2));
        const float sum = __shfl_sync(0xffffffffu, p, 0);
        const float m = __fdiv_rn(sum, 768.0f);

        // ---- variance (EXACT order) ----
        float q = 0.0f;
        if (j < 8) {
#pragma unroll 8
            for (int i = 0; i < 96; i++) {
                const float d = __fsub_rn(xs[w][8 * i + j], m);
                q = __fadd_rn(q, __fmul_rn(d, d));
            }
        }
        q = __fadd_rn(q, __shfl_xor_sync(0xffffffffu, q, 4));
        q = __fadd_rn(q, __shfl_xor_sync(0xffffffffu, q, 1));
        q = __fadd_rn(q, __shfl_xor_sync(0xffffffffu, q, 2));
        const float sum2 = __shfl_sync(0xffffffffu, q, 0);
        const float var = __fdiv_rn(sum2, 768.0f);
        const float rs  = __fsqrt_rn(__fadd_rn(var, 1e-5f));

        // ---- normalize + LIF (EXACT op sequence) ----
#pragma unroll
        for (int k = 0; k < 24; k++) {
            const float x = xs[w][j + 32 * k];
            const float d = __fsub_rn(x, m);
            const float h = __fadd_rn(__fmul_rn(__fdiv_rn(d, rs), gs[j + 32 * k]), bes[j + 32 * k]);
            v[k] = __fadd_rn(v[k], __fdiv_rn(__fsub_rn(h, v[k]), 2.0f));
            const bool f = (__fsub_rn(v[k], thr) >= 0.0f);
            Sout[off + j + 32 * k] = f ? 1.0f : 0.0f;
            v[k] = f ? 0.0f : v[k];
        }
        __syncwarp();
    }
}

// ===== attention + fused LIF2: QK via popcount, AV via dp4a (all exact integers) =====
// Block per (h,b); loops t=0..3 holding LIF membrane in registers; writes spikes to O.
__global__ __launch_bounds__(256, 2) void attn_lif_kernel(
    const float* __restrict__ Sq, const float* __restrict__ Sk,
    const float* __restrict__ Sv, float* __restrict__ O)
{
    __shared__ float Ks[64 * 64];
    __shared__ float Vsf[64 * 64];
    __shared__ __align__(16) unsigned Vs8[64][16];   // [d][mgroup] 4 int8 m's per word
    __shared__ uint2 Km[64];
    const int h = blockIdx.x;
    const int b = blockIdx.y;
    const int col = h * DH_;
    const int l = threadIdx.x;

    float vmem[64];
#pragma unroll
    for (int d = 0; d < 64; d++) vmem[d] = 0.0f;

    for (int t = 0; t < T_; t++) {
        const size_t rowbase = (size_t)(b * T_ + t) * L_;

        // this thread's query-row spike mask (64 bits as 2x u32)
        unsigned qlo = 0u, qhi = 0u;
        {
            const float4* qp = (const float4*)(Sq + (rowbase + l) * D_ + col);
#pragma unroll
            for (int i = 0; i < 8; i++) {
                float4 v4 = qp[i];
                if (v4.x > 0.5f) qlo |= 1u << (4 * i + 0);
                if (v4.y > 0.5f) qlo |= 1u << (4 * i + 1);
                if (v4.z > 0.5f) qlo |= 1u << (4 * i + 2);
                if (v4.w > 0.5f) qlo |= 1u << (4 * i + 3);
            }
#pragma unroll
            for (int i = 8; i < 16; i++) {
                float4 v4 = qp[i];
                if (v4.x > 0.5f) qhi |= 1u << (4 * i - 32 + 0);
                if (v4.y > 0.5f) qhi |= 1u << (4 * i - 32 + 1);
                if (v4.z > 0.5f) qhi |= 1u << (4 * i - 32 + 2);
                if (v4.w > 0.5f) qhi |= 1u << (4 * i - 32 + 3);
            }
        }

        int o32[64];
#pragma unroll
        for (int d = 0; d < 64; d++) o32[d] = 0;

        for (int m0 = 0; m0 < L_; m0 += 64) {
            __syncthreads();
            for (int idx = threadIdx.x; idx < 64 * 64; idx += 256) {
                const int m = idx >> 6;
                const int d = idx & 63;
                const size_t goff = (rowbase + m0 + m) * D_ + col + d;
                Ks[idx]  = Sk[goff];
                Vsf[idx] = Sv[goff];
            }
            __syncthreads();
            // K row masks (64 threads)
            if (threadIdx.x < 64) {
                const int m = threadIdx.x;
                unsigned klo = 0u, khi = 0u;
                const float4* kp = (const float4*)&Ks[m * 64];
#pragma unroll
                for (int i = 0; i < 8; i++) {
                    float4 v4 = kp[i];
                    if (v4.x > 0.5f) klo |= 1u << (4 * i + 0);
                    if (v4.y > 0.5f) klo |= 1u << (4 * i + 1);
                    if (v4.z > 0.5f) klo |= 1u << (4 * i + 2);
                    if (v4.w > 0.5f) klo |= 1u << (4 * i + 3);
                }
#pragma unroll
                for (int i = 8; i < 16; i++) {
                    float4 v4 = kp[i];
                    if (v4.x > 0.5f) khi |= 1u << (4 * i - 32 + 0);
                    if (v4.y > 0.5f) khi |= 1u << (4 * i - 32 + 1);
                    if (v4.z > 0.5f) khi |= 1u << (4 * i - 32 + 2);
                    if (v4.w > 0.5f) khi |= 1u << (4 * i - 32 + 3);
                }
                Km[m] = make_uint2(klo, khi);
            }
            // pack V tile to int8 d-major: Vs8[d][mg] = bytes of m=4mg..4mg+3
            for (int wv = threadIdx.x; wv < 1024; wv += 256) {
                const int d  = wv >> 4;
                const int mg = wv & 15;
                unsigned r = 0;
                if (Vsf[(4 * mg + 0) * 64 + d] > 0.5f) r |= 1u;
                if (Vsf[(4 * mg + 1) * 64 + d] > 0.5f) r |= 1u << 8;
                if (Vsf[(4 * mg + 2) * 64 + d] > 0.5f) r |= 1u << 16;
                if (Vsf[(4 * mg + 3) * 64 + d] > 0.5f) r |= 1u << 24;
                Vs8[d][mg] = r;
            }
            __syncthreads();

#pragma unroll 1
            for (int mq = 0; mq < 4; mq++) {     // 16 m's per mq
                unsigned a4[4];
#pragma unroll
                for (int r = 0; r < 4; r++) {
                    const int mg = mq * 4 + r;
                    const uint2 k0 = Km[4 * mg + 0];
                    const uint2 k1 = Km[4 * mg + 1];
                    const uint2 k2 = Km[4 * mg + 2];
                    const uint2 k3 = Km[4 * mg + 3];
                    const int a0 = __popc(qlo & k0.x) + __popc(qhi & k0.y);
                    const int a1 = __popc(qlo & k1.x) + __popc(qhi & k1.y);
                    const int a2 = __popc(qlo & k2.x) + __popc(qhi & k2.y);
                    const int a3 = __popc(qlo & k3.x) + __popc(qhi & k3.y);
                    a4[r] = (unsigned)a0 | ((unsigned)a1 << 8) |
                            ((unsigned)a2 << 16) | ((unsigned)a3 << 24);
                }
#pragma unroll
                for (int d = 0; d < 64; d++) {
                    const uint4 vv = *(const uint4*)&Vs8[d][mq * 4];
                    int acc = o32[d];
                    acc = __dp4a((int)a4[0], (int)vv.x, acc);
                    acc = __dp4a((int)a4[1], (int)vv.y, acc);
                    acc = __dp4a((int)a4[2], (int)vv.z, acc);
                    acc = __dp4a((int)a4[3], (int)vv.w, acc);
                    o32[d] = acc;
                }
            }
        }

        // fused: x = o*0.25 (exact); LIF thr=0.5 (exact dyadics); write spikes
        float* op = O + (rowbase + l) * D_ + col;
#pragma unroll
        for (int d = 0; d < 64; d++) {
            const float x = __fmul_rn((float)o32[d], 0.25f);
            vmem[d] = __fadd_rn(vmem[d], __fdiv_rn(__fsub_rn(x, vmem[d]), 2.0f));
            const bool f = (__fsub_rn(vmem[d], 0.5f) >= 0.0f);
            op[d] = f ? 1.0f : 0.0f;
            vmem[d] = f ? 0.0f : vmem[d];
        }
    }
}

// ================= launch =================
extern "C" void kernel_launch(void* const* d_in, const int* in_sizes, int n_in,
                              void* d_out, int out_size)
{
    (void)in_sizes; (void)n_in; (void)out_size;
    const float* x   = (const float*)d_in[0];
    const float* qw  = (const float*)d_in[1];
    const float* qb  = (const float*)d_in[2];
    const float* qg  = (const float*)d_in[3];
    const float* qbe = (const float*)d_in[4];
    const float* kw  = (const float*)d_in[5];
    const float* kb  = (const float*)d_in[6];
    const float* kg  = (const float*)d_in[7];
    const float* kbe = (const float*)d_in[8];
    const float* vw  = (const float*)d_in[9];
    const float* vb  = (const float*)d_in[10];
    const float* vg  = (const float*)d_in[11];
    const float* vbe = (const float*)d_in[12];
    const float* lw  = (const float*)d_in[13];
    const float* lb  = (const float*)d_in[14];
    const float* lg  = (const float*)d_in[15];
    const float* lbe = (const float*)d_in[16];

    float *Hq, *Hk, *Hv, *O, *Y;
    cudaGetSymbolAddress((void**)&Hq, g_Hq);
    cudaGetSymbolAddress((void**)&Hk, g_Hk);
    cudaGetSymbolAddress((void**)&Hv, g_Hv);
    cudaGetSymbolAddress((void**)&O,  g_O);
    cudaGetSymbolAddress((void**)&Y,  g_Y);

    const dim3 gemm_grid(D_ / 128, N_ / 128);   // (6, 256)
    const int ln_blocks = (B_ * L_) / 8;

    // projections (single ascending-k fp32 chains)
    gemm_nt_kernel<<<gemm_grid, 256>>>(x, qw, qb, Hq, D_, D_);
    gemm_nt_kernel<<<gemm_grid, 256>>>(x, kw, kb, Hk, D_, D_);
    gemm_nt_kernel<<<gemm_grid, 256>>>(x, vw, vb, Hv, D_, D_);

    // LN + LIF (thr=1), bitwise reduce, in place -> binary spikes
    ln_lif_kernel<<<ln_blocks, 256>>>(Hq, Hq, qg, qbe, 1.0f);
    ln_lif_kernel<<<ln_blocks, 256>>>(Hk, Hk, kg, kbe, 1.0f);
    ln_lif_kernel<<<ln_blocks, 256>>>(Hv, Hv, vg, vbe, 1.0f);

    // attention + fused LIF2 (exact integer math) -> binary spikes in O
    attn_lif_kernel<<<dim3(H_, B_), 256>>>(Hq, Hk, Hv, O);

    // final linear on binary spikes
    gemm_nt_kernel<<<gemm_grid, 256>>>(O, lw, lb, Y, D_, D_);

    // final LN + LIF (thr=1) -> output [B,T,L,D]
    ln_lif_kernel<<<ln_blocks, 256>>>(Y, (float*)d_out, lg, lbe, 1.0f);
}

// round 11
// speedup vs baseline: 1.6348x; 1.6348x over previous
#include <cuda_runtime.h>

#define B_  32
#define T_  4
#define L_  256
#define D_  768
#define H_  12
#define DH_ 64
#define N_  (B_*T_*L_)   // 32768 rows

// ---------------- scratch (no allocations allowed) ----------------
__device__ float g_Hq[(size_t)N_*D_];
__device__ float g_Hk[(size_t)N_*D_];
__device__ float g_Hv[(size_t)N_*D_];
__device__ float g_O [(size_t)N_*D_];
__device__ float g_Y [(size_t)N_*D_];
__device__ unsigned long long g_Mq[(size_t)N_*H_];
__device__ unsigned long long g_Mk[(size_t)N_*H_];
__device__ unsigned long long g_Mv[(size_t)N_*H_];   // written, unused

// ---------------- packed f32x2 helpers (sm_103a) ----------------
__device__ __forceinline__ unsigned long long pack2(float lo, float hi) {
    unsigned long long r;
    asm("mov.b64 %0, {%1, %2};" : "=l"(r) : "f"(lo), "f"(hi));
    return r;
}
__device__ __forceinline__ void unpack2(unsigned long long v, float& lo, float& hi) {
    asm("mov.b64 {%0, %1}, %2;" : "=f"(lo), "=f"(hi) : "l"(v));
}
__device__ __forceinline__ unsigned long long ffma2(
    unsigned long long a, unsigned long long b, unsigned long long c) {
    unsigned long long d;
    asm("fma.rn.f32x2 %0, %1, %2, %3;" : "=l"(d) : "l"(a), "l"(b), "l"(c));
    return d;
}

// ====== GEMM (3-way merged): C[z][m,n] = bias[z][n] + sum_k A[m,k]*W[z][n,k] ======
// Single ascending-k FMA chain per element — bitwise-exact vs reference. DO NOT reorder.
__global__ __launch_bounds__(256) void gemm3_kernel(
    const float* __restrict__ A,
    const float* __restrict__ W0, const float* __restrict__ W1, const float* __restrict__ W2,
    const float* __restrict__ b0, const float* __restrict__ b1, const float* __restrict__ b2,
    float* __restrict__ C0, float* __restrict__ C1, float* __restrict__ C2,
    int K, int Nn)
{
    const float* W    = (blockIdx.z == 0) ? W0 : (blockIdx.z == 1) ? W1 : W2;
    const float* bias = (blockIdx.z == 0) ? b0 : (blockIdx.z == 1) ? b1 : b2;
    float*       C    = (blockIdx.z == 0) ? C0 : (blockIdx.z == 1) ? C1 : C2;

    __shared__ float As[8][128];
    __shared__ float Bs[8][128];
    const int tid  = threadIdx.x;
    const int tx   = tid & 15;
    const int ty   = tid >> 4;
    const int m0   = blockIdx.y * 128;
    const int n0   = blockIdx.x * 128;
    const int arow = tid >> 1;
    const int ak   = (tid & 1) * 4;

    const float* Aptr = A + (size_t)(m0 + arow) * K + ak;
    const float* Wptr = W + (size_t)(n0 + arow) * K + ak;

    unsigned long long acc2[8][4];
#pragma unroll
    for (int i = 0; i < 8; i++)
#pragma unroll
        for (int j = 0; j < 4; j++) acc2[i][j] = 0ULL;

    for (int k0 = 0; k0 < K; k0 += 8) {
        float4 av = *(const float4*)(Aptr + k0);
        float4 wv = *(const float4*)(Wptr + k0);
        __syncthreads();
        As[ak + 0][arow] = av.x; As[ak + 1][arow] = av.y;
        As[ak + 2][arow] = av.z; As[ak + 3][arow] = av.w;
        Bs[ak + 0][arow] = wv.x; Bs[ak + 1][arow] = wv.y;
        Bs[ak + 2][arow] = wv.z; Bs[ak + 3][arow] = wv.w;
        __syncthreads();
#pragma unroll
        for (int kk = 0; kk < 8; kk++) {          // ascending k
            float a[8];
            *(float4*)&a[0] = *(const float4*)&As[kk][ty * 8 + 0];
            *(float4*)&a[4] = *(const float4*)&As[kk][ty * 8 + 4];
            const ulonglong2 b01 = *(const ulonglong2*)&Bs[kk][tx * 8 + 0];
            const ulonglong2 b23 = *(const ulonglong2*)&Bs[kk][tx * 8 + 4];
            unsigned long long b2[4];
            b2[0] = b01.x; b2[1] = b01.y; b2[2] = b23.x; b2[3] = b23.y;
#pragma unroll
            for (int i = 0; i < 8; i++) {
                const unsigned long long a2 = pack2(a[i], a[i]);
#pragma unroll
                for (int j = 0; j < 4; j++)
                    acc2[i][j] = ffma2(a2, b2[j], acc2[i][j]);
            }
        }
    }

#pragma unroll
    for (int i = 0; i < 8; i++) {
        float* cp = C + (size_t)(m0 + ty * 8 + i) * Nn + n0 + tx * 8;
#pragma unroll
        for (int j = 0; j < 4; j++) {
            float c0, c1;
            unpack2(acc2[i][j], c0, c1);
            cp[2 * j + 0] = __fadd_rn(c0, bias[n0 + tx * 8 + 2 * j + 0]);
            cp[2 * j + 1] = __fadd_rn(c1, bias[n0 + tx * 8 + 2 * j + 1]);
        }
    }
}

// ===== LayerNorm + LIF (3-way merged), XLA:CPU NEON-VF8 reduce — order bitwise-fixed =====
// grid.y selects (Hin, Sout, gam, bet, Mout). Sout==null skips float spikes;
// Mout!=null emits per-head packed u64 spike masks via ballot (exact same booleans).
__global__ __launch_bounds__(256) void ln3_kernel(
    const float* __restrict__ H0, const float* __restrict__ H1, const float* __restrict__ H2,
    float* __restrict__ S0, float* __restrict__ S1, float* __restrict__ S2,
    const float* __restrict__ g0_, const float* __restrict__ g1_, const float* __restrict__ g2_,
    const float* __restrict__ e0_, const float* __restrict__ e1_, const float* __restrict__ e2_,
    unsigned long long* __restrict__ M0, unsigned long long* __restrict__ M1,
    unsigned long long* __restrict__ M2, float thr)
{
    const float* Hin = (blockIdx.y == 0) ? H0 : (blockIdx.y == 1) ? H1 : H2;
    float*      Sout = (blockIdx.y == 0) ? S0 : (blockIdx.y == 1) ? S1 : S2;
    const float* gam = (blockIdx.y == 0) ? g0_ : (blockIdx.y == 1) ? g1_ : g2_;
    const float* bet = (blockIdx.y == 0) ? e0_ : (blockIdx.y == 1) ? e1_ : e2_;
    unsigned long long* Mout = (blockIdx.y == 0) ? M0 : (blockIdx.y == 1) ? M1 : M2;

    __shared__ float xs[8][768];
    const int w   = threadIdx.x >> 5;
    const int j   = threadIdx.x & 31;
    const int row0 = blockIdx.x * 8 + w;
    const int b   = row0 / L_;
    const int l   = row0 % L_;

    float g[24], be[24], v[24];
#pragma unroll
    for (int k = 0; k < 24; k++) {
        g[k]  = gam[j + 32 * k];
        be[k] = bet[j + 32 * k];
        v[k]  = 0.0f;
    }

    for (int t = 0; t < T_; t++) {
        const size_t row = (size_t)(b * T_ + t) * L_ + l;
        const size_t off = row * D_;
#pragma unroll
        for (int k = 0; k < 24; k++)
            xs[w][j + 32 * k] = Hin[off + j + 32 * k];
        __syncwarp();

        // ---- mean: 8-lane stride-8 serial partials (EXACT order) ----
        float p = 0.0f;
        if (j < 8) {
#pragma unroll 8
            for (int i = 0; i < 96; i++)
                p = __fadd_rn(p, xs[w][8 * i + j]);
        }
        p = __fadd_rn(p, __shfl_xor_sync(0xffffffffu, p, 4));
        p = __fadd_rn(p, __shfl_xor_sync(0xffffffffu, p, 1));
        p = __fadd_rn(p, __shfl_xor_sync(0xffffffffu, p, 2));
        const float sum = __shfl_sync(0xffffffffu, p, 0);
        const float m = __fdiv_rn(sum, 768.0f);

        // ---- variance (EXACT order) ----
        float q = 0.0f;
        if (j < 8) {
#pragma unroll 8
            for (int i = 0; i < 96; i++) {
                const float d = __fsub_rn(xs[w][8 * i + j], m);
                q = __fadd_rn(q, __fmul_rn(d, d));
            }
        }
        q = __fadd_rn(q, __shfl_xor_sync(0xffffffffu, q, 4));
        q = __fadd_rn(q, __shfl_xor_sync(0xffffffffu, q, 1));
        q = __fadd_rn(q, __shfl_xor_sync(0xffffffffu, q, 2));
        const float sum2 = __shfl_sync(0xffffffffu, q, 0);
        const float var = __fdiv_rn(sum2, 768.0f);
        const float rs  = __fsqrt_rn(__fadd_rn(var, 1e-5f));

        // ---- normalize + LIF (EXACT op sequence) + mask/spike emission ----
        unsigned btmp = 0u;
#pragma unroll
        for (int k = 0; k < 24; k++) {
            const float x = xs[w][j + 32 * k];
            const float d = __fsub_rn(x, m);
            const float h = __fadd_rn(__fmul_rn(__fdiv_rn(d, rs), g[k]), be[k]);
            v[k] = __fadd_rn(v[k], __fdiv_rn(__fsub_rn(h, v[k]), 2.0f));
            const bool f = (__fsub_rn(v[k], thr) >= 0.0f);
            if (Sout) Sout[off + j + 32 * k] = f ? 1.0f : 0.0f;
            v[k] = f ? 0.0f : v[k];
            if (Mout) {
                const unsigned bal = __ballot_sync(0xffffffffu, f);
                if ((k & 1) == 0) btmp = bal;
                else if (j == (k >> 1))
                    Mout[row * H_ + (k >> 1)] =
                        (unsigned long long)btmp | ((unsigned long long)bal << 32);
            }
        }
        __syncwarp();
    }
}

// ===== attention: QK via mask popcount, AV via FFMA2 on float V (exact integers) =====
__global__ __launch_bounds__(256) void attn_kernel(
    const unsigned long long* __restrict__ Mq, const unsigned long long* __restrict__ Mk,
    const float* __restrict__ Sv, float* __restrict__ O)
{
    __shared__ float Vs[64 * 64];
    __shared__ unsigned long long Km[64];
    const int h = blockIdx.x;
    const int t = blockIdx.y;
    const int b = blockIdx.z;
    const size_t rowbase = (size_t)(b * T_ + t) * L_;
    const int col = h * DH_;
    const int l = threadIdx.x;

    const unsigned long long qmask = Mq[(rowbase + l) * H_ + h];

    unsigned long long o2[32];
#pragma unroll
    for (int j = 0; j < 32; j++) o2[j] = 0ULL;

    for (int m0 = 0; m0 < L_; m0 += 64) {
        __syncthreads();
        for (int idx = threadIdx.x; idx < 64 * 64; idx += 256) {
            const int m = idx >> 6;
            const int d = idx & 63;
            Vs[idx] = Sv[(rowbase + m0 + m) * D_ + col + d];
        }
        if (threadIdx.x < 64)
            Km[threadIdx.x] = Mk[(rowbase + m0 + threadIdx.x) * H_ + h];
        __syncthreads();

#pragma unroll 1
        for (int m = 0; m < 64; m++) {
            const float a = (float)__popcll(qmask & Km[m]);   // exact small int
            const unsigned long long a2 = pack2(a, a);
            const ulonglong2* vp = (const ulonglong2*)&Vs[m * 64];
#pragma unroll
            for (int j = 0; j < 16; j++) {
                const ulonglong2 vv = vp[j];
                o2[2 * j + 0] = ffma2(a2, vv.x, o2[2 * j + 0]);
                o2[2 * j + 1] = ffma2(a2, vv.y, o2[2 * j + 1]);
            }
        }
    }

    float* op = O + (rowbase + l) * D_ + col;
#pragma unroll
    for (int j = 0; j < 32; j += 2) {
        float4 v4;
        float f0, f1, f2, f3;
        unpack2(o2[j],     f0, f1);
        unpack2(o2[j + 1], f2, f3);
        v4.x = f0 * 0.25f; v4.y = f1 * 0.25f;   // exact dyadic scaling
        v4.z = f2 * 0.25f; v4.w = f3 * 0.25f;
        *(float4*)(op + 2 * j) = v4;
    }
}

// ========== LIF over T on O (thr = 0.5, exact dyadic), in place ==========
__global__ __launch_bounds__(256) void lif2_kernel(float* __restrict__ IO)
{
    const int idx = blockIdx.x * 256 + threadIdx.x;   // over B*L*D
    const int b = idx / (L_ * D_);
    const int r = idx % (L_ * D_);
    float v = 0.0f;
#pragma unroll
    for (int t = 0; t < T_; t++) {
        const size_t off = ((size_t)(b * T_ + t)) * (size_t)(L_ * D_) + r;
        const float x = IO[off];
        v = __fadd_rn(v, __fdiv_rn(__fsub_rn(x, v), 2.0f));
        const bool f = (__fsub_rn(v, 0.5f) >= 0.0f);
        IO[off] = f ? 1.0f : 0.0f;
        v = f ? 0.0f : v;
    }
}

// ================= launch =================
extern "C" void kernel_launch(void* const* d_in, const int* in_sizes, int n_in,
                              void* d_out, int out_size)
{
    (void)in_sizes; (void)n_in; (void)out_size;
    const float* x   = (const float*)d_in[0];
    const float* qw  = (const float*)d_in[1];
    const float* qb  = (const float*)d_in[2];
    const float* qg  = (const float*)d_in[3];
    const float* qbe = (const float*)d_in[4];
    const float* kw  = (const float*)d_in[5];
    const float* kb  = (const float*)d_in[6];
    const float* kg  = (const float*)d_in[7];
    const float* kbe = (const float*)d_in[8];
    const float* vw  = (const float*)d_in[9];
    const float* vb  = (const float*)d_in[10];
    const float* vg  = (const float*)d_in[11];
    const float* vbe = (const float*)d_in[12];
    const float* lw  = (const float*)d_in[13];
    const float* lb  = (const float*)d_in[14];
    const float* lg  = (const float*)d_in[15];
    const float* lbe = (const float*)d_in[16];

    float *Hq, *Hk, *Hv, *O, *Y;
    unsigned long long *Mq, *Mk, *Mv;
    cudaGetSymbolAddress((void**)&Hq, g_Hq);
    cudaGetSymbolAddress((void**)&Hk, g_Hk);
    cudaGetSymbolAddress((void**)&Hv, g_Hv);
    cudaGetSymbolAddress((void**)&O,  g_O);
    cudaGetSymbolAddress((void**)&Y,  g_Y);
    cudaGetSymbolAddress((void**)&Mq, g_Mq);
    cudaGetSymbolAddress((void**)&Mk, g_Mk);
    cudaGetSymbolAddress((void**)&Mv, g_Mv);

    // Q/K/V projections in ONE launch (amortize wave tail)
    gemm3_kernel<<<dim3(D_ / 128, N_ / 128, 3), 256>>>(
        x, qw, kw, vw, qb, kb, vb, Hq, Hk, Hv, D_, D_);

    // 3 LNs in ONE launch: Q,K emit masks only (no float spikes); V emits floats + mask
    ln3_kernel<<<dim3((B_ * L_) / 8, 3), 256>>>(
        Hq, Hk, Hv,
        nullptr, nullptr, Hv,
        qg, kg, vg, qbe, kbe, vbe,
        Mq, Mk, Mv, 1.0f);

    // attention per (h,t,b) — mask QK + float-FFMA2 AV (exact integers)
    attn_kernel<<<dim3(H_, T_, B_), 256>>>(Mq, Mk, Hv, O);

    // LIF (thr=0.5) over T, exact dyadic, in place -> binary
    lif2_kernel<<<(B_ * L_ * D_) / 256, 256>>>(O);

    // final linear on binary spikes (single-slice use of merged kernel)
    gemm3_kernel<<<dim3(D_ / 128, N_ / 128, 1), 256>>>(
        O, lw, lw, lw, lb, lb, lb, Y, Y, Y, D_, D_);

    // final LN + LIF (thr=1) -> output [B,T,L,D]; no masks
    ln3_kernel<<<dim3((B_ * L_) / 8, 1), 256>>>(
        Y, Y, Y,
        (float*)d_out, (float*)d_out, (float*)d_out,
        lg, lg, lg, lbe, lbe, lbe,
        nullptr, nullptr, nullptr, 1.0f);
}